// round 1
// baseline (speedup 1.0000x reference)
#include <cuda_runtime.h>
#include <math.h>

#define T_TOKENS 131072   // 32 * 64 * 64
#define CDIM 128

// ---------------- scratch (device globals, no allocation) ----------------
__device__ float g_xr [T_TOKENS * 128];   // 64 MB
__device__ float g_ln [T_TOKENS * 128];   // 64 MB
__device__ float g_qkv[T_TOKENS * 384];   // 192 MB
__device__ float g_att[T_TOKENS * 128];   // 64 MB
__device__ float g_h  [T_TOKENS * 512];   // 256 MB

// ---------------- transpose (B,C,HW) -> (B,HW,C) ----------------
__global__ void k_transpose(const float* __restrict__ x, float* __restrict__ xr) {
    __shared__ float tile[32][33];
    int b  = blockIdx.z;
    int s0 = blockIdx.x * 32;   // hw
    int c0 = blockIdx.y * 32;   // channel
    const float* xb = x + (size_t)b * 128 * 4096;
    int tx = threadIdx.x, ty = threadIdx.y;  // 32 x 8
#pragma unroll
    for (int i = 0; i < 32; i += 8)
        tile[ty + i][tx] = xb[(size_t)(c0 + ty + i) * 4096 + s0 + tx];
    __syncthreads();
    float* xrb = xr + (size_t)b * 4096 * 128;
#pragma unroll
    for (int i = 0; i < 32; i += 8)
        xrb[(size_t)(s0 + ty + i) * 128 + c0 + tx] = tile[tx][ty + i];
}

// ---------------- LayerNorm: one warp per token (C=128) ----------------
__global__ void k_ln(const float* __restrict__ in, const float* __restrict__ g,
                     const float* __restrict__ bta, float* __restrict__ out) {
    int warp = (blockIdx.x * blockDim.x + threadIdx.x) >> 5;
    int lane = threadIdx.x & 31;
    if (warp >= T_TOKENS) return;
    float4 v = ((const float4*)(in + (size_t)warp * 128))[lane];
    float s = v.x + v.y + v.z + v.w;
#pragma unroll
    for (int o = 16; o; o >>= 1) s += __shfl_xor_sync(0xffffffffu, s, o);
    float mu = s * (1.0f / 128.0f);
    float dx = v.x - mu, dy = v.y - mu, dz = v.z - mu, dw = v.w - mu;
    float q = dx * dx + dy * dy + dz * dz + dw * dw;
#pragma unroll
    for (int o = 16; o; o >>= 1) q += __shfl_xor_sync(0xffffffffu, q, o);
    float inv = rsqrtf(q * (1.0f / 128.0f) + 1e-5f);
    float4 gv = ((const float4*)g)[lane];
    float4 bv = ((const float4*)bta)[lane];
    float4 o4;
    o4.x = dx * inv * gv.x + bv.x;
    o4.y = dy * inv * gv.y + bv.y;
    o4.z = dz * inv * gv.z + bv.z;
    o4.w = dw * inv * gv.w + bv.w;
    ((float4*)(out + (size_t)warp * 128))[lane] = o4;
}

// ---------------- SGEMM: C[M,N] = A[M,K] @ B[K,N] + bias (+res) (gelu) ----------------
// BM=BN=64, BK=16, 256 threads, 4x4 microtile. M%64==0, N%64==0, K%16==0.
__device__ __forceinline__ float gelu_exact(float x) {
    return 0.5f * x * (1.0f + erff(x * 0.70710678118654752f));
}

template <int ACT, bool RES>
__global__ __launch_bounds__(256)
void k_gemm(const float* __restrict__ A, const float* __restrict__ B,
            const float* __restrict__ bias, const float* __restrict__ res,
            float* __restrict__ C, int M, int N, int K) {
    __shared__ float As[16][64];
    __shared__ float Bs[16][64];
    int bm = blockIdx.x * 64, bn = blockIdx.y * 64;
    int tid = threadIdx.x;
    int tm = (tid / 16) * 4, tn = (tid % 16) * 4;
    int ar = tid / 4;            // 0..63 (A row in tile)
    int ac = (tid % 4) * 4;      // 0,4,8,12 (k offset)
    int br = tid / 16;           // 0..15 (k row)
    int bc = (tid % 16) * 4;     // n offset
    float acc[4][4] = {};
    for (int k0 = 0; k0 < K; k0 += 16) {
        float4 av = *(const float4*)(A + (size_t)(bm + ar) * K + k0 + ac);
        As[ac + 0][ar] = av.x; As[ac + 1][ar] = av.y;
        As[ac + 2][ar] = av.z; As[ac + 3][ar] = av.w;
        *(float4*)&Bs[br][bc] = *(const float4*)(B + (size_t)(k0 + br) * N + bn + bc);
        __syncthreads();
#pragma unroll
        for (int kk = 0; kk < 16; ++kk) {
            float4 a = *(const float4*)&As[kk][tm];
            float4 b = *(const float4*)&Bs[kk][tn];
            acc[0][0] += a.x * b.x; acc[0][1] += a.x * b.y; acc[0][2] += a.x * b.z; acc[0][3] += a.x * b.w;
            acc[1][0] += a.y * b.x; acc[1][1] += a.y * b.y; acc[1][2] += a.y * b.z; acc[1][3] += a.y * b.w;
            acc[2][0] += a.z * b.x; acc[2][1] += a.z * b.y; acc[2][2] += a.z * b.z; acc[2][3] += a.z * b.w;
            acc[3][0] += a.w * b.x; acc[3][1] += a.w * b.y; acc[3][2] += a.w * b.z; acc[3][3] += a.w * b.w;
        }
        __syncthreads();
    }
    float4 bb = *(const float4*)(bias + bn + tn);
#pragma unroll
    for (int i = 0; i < 4; ++i) {
        size_t off = (size_t)(bm + tm + i) * N + bn + tn;
        float4 o;
        o.x = acc[i][0] + bb.x; o.y = acc[i][1] + bb.y;
        o.z = acc[i][2] + bb.z; o.w = acc[i][3] + bb.w;
        if (ACT == 1) {
            o.x = gelu_exact(o.x); o.y = gelu_exact(o.y);
            o.z = gelu_exact(o.z); o.w = gelu_exact(o.w);
        }
        if (RES) {
            float4 r = *(const float4*)(res + off);
            o.x += r.x; o.y += r.y; o.z += r.z; o.w += r.w;
        }
        *(float4*)(C + off) = o;
    }
}

// ---------------- window attention (ws=2, n=4, heads=4, e=32) ----------------
// block = 128 threads = 4 warps (one per head), grid = B*32*32 windows.
// qkv channel layout: col = (e*4 + head)*3 + {0,1,2}; output channel = head*32 + e.
__global__ __launch_bounds__(128)
void k_attn(const float* __restrict__ qkv, const float* __restrict__ pos,
            float* __restrict__ att, int shifted) {
    int wid = blockIdx.x;
    int ww = wid & 31, wh = (wid >> 5) & 31, b = wid >> 10;
    __shared__ float s[4][384];
    __shared__ float spos[9];
    int tid = threadIdx.x;
    if (tid < 9) spos[tid] = pos[tid];
    // cooperative load of the 4 tokens' qkv rows (gather shifted source)
    {
        int i = tid >> 5, lane = tid & 31;
        int lh = i >> 1, lw = i & 1;
        int h = wh * 2 + lh, w = ww * 2 + lw;
        if (shifted) { h = (h + 1) & 63; w = (w + 1) & 63; }
        size_t t = (size_t)b * 4096 + h * 64 + w;
        const float* src = qkv + t * 384;
#pragma unroll
        for (int j = 0; j < 12; ++j) s[i][lane + j * 32] = src[lane + j * 32];
    }
    __syncthreads();

    int head = tid >> 5, lane = tid & 31;
    float q[4], k[4], v[4];
#pragma unroll
    for (int i = 0; i < 4; ++i) {
        int base = (lane * 4 + head) * 3;
        q[i] = s[i][base]; k[i] = s[i][base + 1]; v[i] = s[i][base + 2];
    }
    const float scale = 0.17677669529663687f;  // 1/sqrt(32)
    float sc[4][4];
#pragma unroll
    for (int i = 0; i < 4; ++i)
#pragma unroll
        for (int j = 0; j < 4; ++j) {
            float p = q[i] * k[j];
#pragma unroll
            for (int o = 16; o; o >>= 1) p += __shfl_xor_sync(0xffffffffu, p, o);
            int dx = (j >> 1) - (i >> 1) + 1;
            int dy = (j & 1) - (i & 1) + 1;
            float w = p * scale + spos[dx * 3 + dy];
            if (shifted) {
                if (wh == 31 && ((i >> 1) != (j >> 1))) w = -1e30f;
                if (ww == 31 && ((i & 1) != (j & 1))) w = -1e30f;
            }
            sc[i][j] = w;
        }
    // softmax rows + weighted sum of v
    float out[4];
#pragma unroll
    for (int i = 0; i < 4; ++i) {
        float m = fmaxf(fmaxf(sc[i][0], sc[i][1]), fmaxf(sc[i][2], sc[i][3]));
        float e0 = expf(sc[i][0] - m), e1 = expf(sc[i][1] - m);
        float e2 = expf(sc[i][2] - m), e3 = expf(sc[i][3] - m);
        float inv = 1.0f / (e0 + e1 + e2 + e3);
        out[i] = (e0 * v[0] + e1 * v[1] + e2 * v[2] + e3 * v[3]) * inv;
    }
    // write at (unshifted) window positions; output channel = head*32 + e
#pragma unroll
    for (int i = 0; i < 4; ++i) {
        int lh = i >> 1, lw = i & 1;
        int h = wh * 2 + lh, w = ww * 2 + lw;
        size_t t = (size_t)b * 4096 + h * 64 + w;
        att[t * 128 + head * 32 + lane] = out[i];
    }
}

// ---------------- host orchestration ----------------
extern "C" void kernel_launch(void* const* d_in, const int* in_sizes, int n_in,
                              void* d_out, int out_size) {
    const float* x    = (const float*)d_in[0];
    const float* ln_g = (const float*)d_in[1];
    const float* ln_b = (const float*)d_in[2];
    const float* wq_W = (const float*)d_in[3];
    const float* wq_b = (const float*)d_in[4];
    const float* wp_W = (const float*)d_in[5];
    const float* wp_b = (const float*)d_in[6];
    const float* wpos = (const float*)d_in[7];
    const float* sq_W = (const float*)d_in[8];
    const float* sq_b = (const float*)d_in[9];
    const float* sp_W = (const float*)d_in[10];
    const float* sp_b = (const float*)d_in[11];
    const float* spos = (const float*)d_in[12];
    const float* m1_W = (const float*)d_in[13];
    const float* m1_b = (const float*)d_in[14];
    const float* m2_W = (const float*)d_in[15];
    const float* m2_b = (const float*)d_in[16];
    float* y = (float*)d_out;

    float *p_xr, *p_ln, *p_qkv, *p_att, *p_h;
    cudaGetSymbolAddress((void**)&p_xr,  g_xr);
    cudaGetSymbolAddress((void**)&p_ln,  g_ln);
    cudaGetSymbolAddress((void**)&p_qkv, g_qkv);
    cudaGetSymbolAddress((void**)&p_att, g_att);
    cudaGetSymbolAddress((void**)&p_h,   g_h);

    const int M = T_TOKENS;
    dim3 tgrid(128, 4, 32), tblk(32, 8);
    int lnGrid = T_TOKENS / 8;  // 8 warps/block

    // xr = transpose(x); ln = LN(xr)
    k_transpose<<<tgrid, tblk>>>(x, p_xr);
    k_ln<<<lnGrid, 256>>>(p_xr, ln_g, ln_b, p_ln);

    // ---- block 1: W-MSA ----
    k_gemm<0, false><<<dim3(M / 64, 6), 256>>>(p_ln, wq_W, wq_b, nullptr, p_qkv, M, 384, 128);
    k_attn<<<32768, 128>>>(p_qkv, wpos, p_att, 0);
    k_gemm<0, true><<<dim3(M / 64, 2), 256>>>(p_att, wp_W, wp_b, p_xr, y, M, 128, 128);
    // MLP
    k_ln<<<lnGrid, 256>>>(y, ln_g, ln_b, p_ln);
    k_gemm<1, false><<<dim3(M / 64, 8), 256>>>(p_ln, m1_W, m1_b, nullptr, p_h, M, 512, 128);
    k_gemm<0, true><<<dim3(M / 64, 2), 256>>>(p_h, m2_W, m2_b, y, y, M, 128, 512);

    // ---- block 2: SW-MSA ----
    k_ln<<<lnGrid, 256>>>(y, ln_g, ln_b, p_ln);
    k_gemm<0, false><<<dim3(M / 64, 6), 256>>>(p_ln, sq_W, sq_b, nullptr, p_qkv, M, 384, 128);
    k_attn<<<32768, 128>>>(p_qkv, spos, p_att, 1);
    k_gemm<0, true><<<dim3(M / 64, 2), 256>>>(p_att, sp_W, sp_b, y, y, M, 128, 128);
    // MLP
    k_ln<<<lnGrid, 256>>>(y, ln_g, ln_b, p_ln);
    k_gemm<1, false><<<dim3(M / 64, 8), 256>>>(p_ln, m1_W, m1_b, nullptr, p_h, M, 512, 128);
    k_gemm<0, true><<<dim3(M / 64, 2), 256>>>(p_h, m2_W, m2_b, y, y, M, 128, 512);
}

// round 3
// speedup vs baseline: 2.1687x; 2.1687x over previous
#include <cuda_runtime.h>
#include <math.h>

#define T_TOKENS 131072   // 32 * 64 * 64

// ---------------- scratch (device globals, no allocation) ----------------
__device__ float g_xr [T_TOKENS * 128];   // 64 MB
__device__ float g_ln [T_TOKENS * 128];   // 64 MB
__device__ float g_qkv[T_TOKENS * 384];   // 192 MB
__device__ float g_att[T_TOKENS * 128];   // 64 MB
__device__ float g_h  [T_TOKENS * 512];   // 256 MB

// ---------------- transpose (B,C,HW) -> (B,HW,C) ----------------
__global__ void k_transpose(const float* __restrict__ x, float* __restrict__ xr) {
    __shared__ float tile[32][33];
    int b  = blockIdx.z;
    int s0 = blockIdx.x * 32;   // hw
    int c0 = blockIdx.y * 32;   // channel
    const float* xb = x + (size_t)b * 128 * 4096;
    int tx = threadIdx.x, ty = threadIdx.y;  // 32 x 8
#pragma unroll
    for (int i = 0; i < 32; i += 8)
        tile[ty + i][tx] = xb[(size_t)(c0 + ty + i) * 4096 + s0 + tx];
    __syncthreads();
    float* xrb = xr + (size_t)b * 4096 * 128;
#pragma unroll
    for (int i = 0; i < 32; i += 8)
        xrb[(size_t)(s0 + ty + i) * 128 + c0 + tx] = tile[tx][ty + i];
}

// ---------------- LayerNorm: one warp per token (C=128) ----------------
__global__ void k_ln(const float* __restrict__ in, const float* __restrict__ g,
                     const float* __restrict__ bta, float* __restrict__ out) {
    int warp = (blockIdx.x * blockDim.x + threadIdx.x) >> 5;
    int lane = threadIdx.x & 31;
    if (warp >= T_TOKENS) return;
    float4 v = ((const float4*)(in + (size_t)warp * 128))[lane];
    float s = v.x + v.y + v.z + v.w;
#pragma unroll
    for (int o = 16; o; o >>= 1) s += __shfl_xor_sync(0xffffffffu, s, o);
    float mu = s * (1.0f / 128.0f);
    float dx = v.x - mu, dy = v.y - mu, dz = v.z - mu, dw = v.w - mu;
    float q = dx * dx + dy * dy + dz * dz + dw * dw;
#pragma unroll
    for (int o = 16; o; o >>= 1) q += __shfl_xor_sync(0xffffffffu, q, o);
    float inv = rsqrtf(q * (1.0f / 128.0f) + 1e-5f);
    float4 gv = ((const float4*)g)[lane];
    float4 bv = ((const float4*)bta)[lane];
    float4 o4;
    o4.x = dx * inv * gv.x + bv.x;
    o4.y = dy * inv * gv.y + bv.y;
    o4.z = dz * inv * gv.z + bv.z;
    o4.w = dw * inv * gv.w + bv.w;
    ((float4*)(out + (size_t)warp * 128))[lane] = o4;
}

// ---------------- tf32 tensor-core GEMM ----------------
// C[M,N] = A[M,K] @ B[K,N] + bias (+gelu) (+res). M%128==0, N%128==0, K%32==0.
// BM=128, BN=128, BK=32, 256 threads, warp tile 32x64 via mma.m16n8k8.tf32.

__device__ __forceinline__ unsigned f2tf32(float x) {
    unsigned r; asm("cvt.rna.tf32.f32 %0, %1;" : "=r"(r) : "f"(x)); return r;
}

__device__ __forceinline__ void mma_tf32(float c[4], const unsigned a[4], const unsigned b[2]) {
    asm volatile(
        "mma.sync.aligned.m16n8k8.row.col.f32.tf32.tf32.f32 "
        "{%0,%1,%2,%3}, {%4,%5,%6,%7}, {%8,%9}, {%0,%1,%2,%3};\n"
        : "+f"(c[0]), "+f"(c[1]), "+f"(c[2]), "+f"(c[3])
        : "r"(a[0]), "r"(a[1]), "r"(a[2]), "r"(a[3]), "r"(b[0]), "r"(b[1]));
}

__device__ __forceinline__ float gelu_exact(float x) {
    return 0.5f * x * (1.0f + erff(x * 0.70710678118654752f));
}

template <int ACT, bool RES>
__global__ __launch_bounds__(256)
void k_gemm_t(const float* __restrict__ A, const float* __restrict__ B,
              const float* __restrict__ bias, const float* __restrict__ res,
              float* __restrict__ C, int M, int N, int K) {
    __shared__ float As[128][36];   // row-major, pad 4: STS128 + frag LDS conflict-free
    __shared__ float Bs[32][136];   // row-major, stride%32==8: conflict-free

    const int tid  = threadIdx.x;
    const int lane = tid & 31;
    const int wid  = tid >> 5;
    const int wm   = (wid >> 1) * 32;   // warp M base: 0,32,64,96
    const int wn   = (wid & 1) * 64;    // warp N base: 0,64
    const int g    = lane >> 2;         // 0..7
    const int tg   = lane & 3;          // 0..3
    const size_t bm = (size_t)blockIdx.x * 128;
    const size_t bn = (size_t)blockIdx.y * 128;

    // global load mapping
    const int am  = tid >> 3;           // 0..31 (row within 32-row pass)
    const int ak  = (tid & 7) * 4;      // k offset (float4)
    const int bk  = tid >> 5;           // 0..7 (k row within 8-row pass)
    const int bnn = (tid & 31) * 4;     // n offset (float4)

    const float* Ag = A + (bm + am) * (size_t)K + ak;
    const float* Bg = B + (size_t)bk * N + bn + bnn;

    float acc[2][8][4];
#pragma unroll
    for (int i = 0; i < 2; ++i)
#pragma unroll
        for (int j = 0; j < 8; ++j)
#pragma unroll
            for (int r = 0; r < 4; ++r) acc[i][j][r] = 0.f;

    const int KT = K >> 5;

    // preload tile 0
#pragma unroll
    for (int p = 0; p < 4; ++p) {
        *(float4*)&As[am + p * 32][ak] = *(const float4*)(Ag + (size_t)(p * 32) * K);
        *(float4*)&Bs[bk + p * 8][bnn] = *(const float4*)(Bg + (size_t)(p * 8) * N);
    }
    __syncthreads();

    for (int kt = 0; kt < KT; ++kt) {
        float4 pa[4], pb[4];
        const bool nxt = (kt + 1 < KT);
        if (nxt) {
            const float* An = Ag + (size_t)(kt + 1) * 32;
            const float* Bn = Bg + (size_t)(kt + 1) * 32 * N;
#pragma unroll
            for (int p = 0; p < 4; ++p) {
                pa[p] = *(const float4*)(An + (size_t)(p * 32) * K);
                pb[p] = *(const float4*)(Bn + (size_t)(p * 8) * N);
            }
        }
#pragma unroll
        for (int ks = 0; ks < 4; ++ks) {
            const int kk = ks * 8;
            unsigned af[2][4];
#pragma unroll
            for (int mi = 0; mi < 2; ++mi) {
                const int m0 = wm + mi * 16 + g;
                af[mi][0] = f2tf32(As[m0    ][kk + tg]);
                af[mi][1] = f2tf32(As[m0 + 8][kk + tg]);
                af[mi][2] = f2tf32(As[m0    ][kk + tg + 4]);
                af[mi][3] = f2tf32(As[m0 + 8][kk + tg + 4]);
            }
            unsigned bf[8][2];
#pragma unroll
            for (int ni = 0; ni < 8; ++ni) {
                const int n0 = wn + ni * 8 + g;
                bf[ni][0] = f2tf32(Bs[kk + tg    ][n0]);
                bf[ni][1] = f2tf32(Bs[kk + tg + 4][n0]);
            }
#pragma unroll
            for (int mi = 0; mi < 2; ++mi)
#pragma unroll
                for (int ni = 0; ni < 8; ++ni)
                    mma_tf32(acc[mi][ni], af[mi], bf[ni]);
        }
        __syncthreads();
        if (nxt) {
#pragma unroll
            for (int p = 0; p < 4; ++p) {
                *(float4*)&As[am + p * 32][ak] = pa[p];
                *(float4*)&Bs[bk + p * 8][bnn] = pb[p];
            }
            __syncthreads();
        }
    }

    // epilogue
#pragma unroll
    for (int mi = 0; mi < 2; ++mi) {
        const size_t r0 = bm + wm + mi * 16 + g;
#pragma unroll
        for (int ni = 0; ni < 8; ++ni) {
            const size_t c0 = bn + wn + ni * 8 + 2 * tg;
            const float bx = bias[c0], by = bias[c0 + 1];
            float v0 = acc[mi][ni][0] + bx, v1 = acc[mi][ni][1] + by;
            float v2 = acc[mi][ni][2] + bx, v3 = acc[mi][ni][3] + by;
            if (ACT == 1) {
                v0 = gelu_exact(v0); v1 = gelu_exact(v1);
                v2 = gelu_exact(v2); v3 = gelu_exact(v3);
            }
            const size_t o0 = r0 * N + c0;
            const size_t o1 = (r0 + 8) * N + c0;
            if (RES) {
                float2 ra = *(const float2*)(res + o0);
                float2 rb = *(const float2*)(res + o1);
                v0 += ra.x; v1 += ra.y; v2 += rb.x; v3 += rb.y;
            }
            float2 w0; w0.x = v0; w0.y = v1;
            float2 w1; w1.x = v2; w1.y = v3;
            *(float2*)(C + o0) = w0;
            *(float2*)(C + o1) = w1;
        }
    }
}

// ---------------- window attention (ws=2, n=4, heads=4, e=32) ----------------
__global__ __launch_bounds__(128)
void k_attn(const float* __restrict__ qkv, const float* __restrict__ pos,
            float* __restrict__ att, int shifted) {
    int wid = blockIdx.x;
    int ww = wid & 31, wh = (wid >> 5) & 31, b = wid >> 10;
    __shared__ float s[4][384];
    __shared__ float spos[9];
    int tid = threadIdx.x;
    if (tid < 9) spos[tid] = pos[tid];
    {
        int i = tid >> 5, lane = tid & 31;
        int lh = i >> 1, lw = i & 1;
        int h = wh * 2 + lh, w = ww * 2 + lw;
        if (shifted) { h = (h + 1) & 63; w = (w + 1) & 63; }
        size_t t = (size_t)b * 4096 + h * 64 + w;
        const float* src = qkv + t * 384;
#pragma unroll
        for (int j = 0; j < 12; ++j) s[i][lane + j * 32] = src[lane + j * 32];
    }
    __syncthreads();

    int head = tid >> 5, lane = tid & 31;
    float q[4], k[4], v[4];
#pragma unroll
    for (int i = 0; i < 4; ++i) {
        int base = (lane * 4 + head) * 3;
        q[i] = s[i][base]; k[i] = s[i][base + 1]; v[i] = s[i][base + 2];
    }
    const float scale = 0.17677669529663687f;  // 1/sqrt(32)
    float sc[4][4];
#pragma unroll
    for (int i = 0; i < 4; ++i)
#pragma unroll
        for (int j = 0; j < 4; ++j) {
            float p = q[i] * k[j];
#pragma unroll
            for (int o = 16; o; o >>= 1) p += __shfl_xor_sync(0xffffffffu, p, o);
            int dx = (j >> 1) - (i >> 1) + 1;
            int dy = (j & 1) - (i & 1) + 1;
            float w = p * scale + spos[dx * 3 + dy];
            if (shifted) {
                if (wh == 31 && ((i >> 1) != (j >> 1))) w = -1e30f;
                if (ww == 31 && ((i & 1) != (j & 1))) w = -1e30f;
            }
            sc[i][j] = w;
        }
    float out[4];
#pragma unroll
    for (int i = 0; i < 4; ++i) {
        float m = fmaxf(fmaxf(sc[i][0], sc[i][1]), fmaxf(sc[i][2], sc[i][3]));
        float e0 = expf(sc[i][0] - m), e1 = expf(sc[i][1] - m);
        float e2 = expf(sc[i][2] - m), e3 = expf(sc[i][3] - m);
        float inv = 1.0f / (e0 + e1 + e2 + e3);
        out[i] = (e0 * v[0] + e1 * v[1] + e2 * v[2] + e3 * v[3]) * inv;
    }
#pragma unroll
    for (int i = 0; i < 4; ++i) {
        int lh = i >> 1, lw = i & 1;
        int h = wh * 2 + lh, w = ww * 2 + lw;
        size_t t = (size_t)b * 4096 + h * 64 + w;
        att[t * 128 + head * 32 + lane] = out[i];
    }
}

// ---------------- host orchestration ----------------
extern "C" void kernel_launch(void* const* d_in, const int* in_sizes, int n_in,
                              void* d_out, int out_size) {
    const float* x    = (const float*)d_in[0];
    const float* ln_g = (const float*)d_in[1];
    const float* ln_b = (const float*)d_in[2];
    const float* wq_W = (const float*)d_in[3];
    const float* wq_b = (const float*)d_in[4];
    const float* wp_W = (const float*)d_in[5];
    const float* wp_b = (const float*)d_in[6];
    const float* wpos = (const float*)d_in[7];
    const float* sq_W = (const float*)d_in[8];
    const float* sq_b = (const float*)d_in[9];
    const float* sp_W = (const float*)d_in[10];
    const float* sp_b = (const float*)d_in[11];
    const float* spos = (const float*)d_in[12];
    const float* m1_W = (const float*)d_in[13];
    const float* m1_b = (const float*)d_in[14];
    const float* m2_W = (const float*)d_in[15];
    const float* m2_b = (const float*)d_in[16];
    float* y = (float*)d_out;

    float *p_xr, *p_ln, *p_qkv, *p_att, *p_h;
    cudaGetSymbolAddress((void**)&p_xr,  g_xr);
    cudaGetSymbolAddress((void**)&p_ln,  g_ln);
    cudaGetSymbolAddress((void**)&p_qkv, g_qkv);
    cudaGetSymbolAddress((void**)&p_att, g_att);
    cudaGetSymbolAddress((void**)&p_h,   g_h);

    const int M = T_TOKENS;
    dim3 tgrid(128, 4, 32), tblk(32, 8);
    int lnGrid = T_TOKENS / 8;  // 8 warps/block

    k_transpose<<<tgrid, tblk>>>(x, p_xr);
    k_ln<<<lnGrid, 256>>>(p_xr, ln_g, ln_b, p_ln);

    // ---- block 1: W-MSA ----
    k_gemm_t<0, false><<<dim3(M / 128, 3), 256>>>(p_ln, wq_W, wq_b, nullptr, p_qkv, M, 384, 128);
    k_attn<<<32768, 128>>>(p_qkv, wpos, p_att, 0);
    k_gemm_t<0, true><<<dim3(M / 128, 1), 256>>>(p_att, wp_W, wp_b, p_xr, y, M, 128, 128);
    // MLP
    k_ln<<<lnGrid, 256>>>(y, ln_g, ln_b, p_ln);
    k_gemm_t<1, false><<<dim3(M / 128, 4), 256>>>(p_ln, m1_W, m1_b, nullptr, p_h, M, 512, 128);
    k_gemm_t<0, true><<<dim3(M / 128, 1), 256>>>(p_h, m2_W, m2_b, y, y, M, 128, 512);

    // ---- block 2: SW-MSA ----
    k_ln<<<lnGrid, 256>>>(y, ln_g, ln_b, p_ln);
    k_gemm_t<0, false><<<dim3(M / 128, 3), 256>>>(p_ln, sq_W, sq_b, nullptr, p_qkv, M, 384, 128);
    k_attn<<<32768, 128>>>(p_qkv, spos, p_att, 1);
    k_gemm_t<0, true><<<dim3(M / 128, 1), 256>>>(p_att, sp_W, sp_b, y, y, M, 128, 128);
    // MLP
    k_ln<<<lnGrid, 256>>>(y, ln_g, ln_b, p_ln);
    k_gemm_t<1, false><<<dim3(M / 128, 4), 256>>>(p_ln, m1_W, m1_b, nullptr, p_h, M, 512, 128);
    k_gemm_t<0, true><<<dim3(M / 128, 1), 256>>>(p_h, m2_W, m2_b, y, y, M, 128, 512);
}